// round 7
// baseline (speedup 1.0000x reference)
#include <cuda_runtime.h>
#include <math.h>

#define Bsz 512
#define Fsz 128
#define Dsz 1024
#define MN (Bsz * Dsz)
#define SPLITK 8

// ---------------- scratch (no allocs allowed -> __device__ globals) ----------
__device__ float g_tln[MN];
__device__ float g_q[MN];
__device__ float g_qp[MN];
__device__ float g_cb[Bsz];
__device__ float g_s[MN];
__device__ float g_attn[MN];
__device__ float g_y[MN];
__device__ float g_aln[MN];
__device__ float g_z[MN];
__device__ float g_part[(size_t)SPLITK * MN];

// ---------------- row LayerNorm over D=1024, 256 threads, float4/thread -----
__global__ __launch_bounds__(256) void ln_rows(const float* __restrict__ X,
                                               float* __restrict__ Y,
                                               const float* __restrict__ gam,
                                               const float* __restrict__ bet) {
    __shared__ float red[2][8];
    const int row = blockIdx.x, tid = threadIdx.x;
    const int lane = tid & 31, w = tid >> 5;
    const float* xr = X + (size_t)row * Dsz;
    float4 x = *(const float4*)(xr + tid * 4);
    float ps = x.x + x.y + x.z + x.w;
    float pq = x.x * x.x + x.y * x.y + x.z * x.z + x.w * x.w;
#pragma unroll
    for (int o = 16; o; o >>= 1) {
        ps += __shfl_xor_sync(0xffffffffu, ps, o);
        pq += __shfl_xor_sync(0xffffffffu, pq, o);
    }
    if (lane == 0) { red[0][w] = ps; red[1][w] = pq; }
    __syncthreads();
    float S = 0.f, Q = 0.f;
#pragma unroll
    for (int i = 0; i < 8; ++i) { S += red[0][i]; Q += red[1][i]; }
    const float mu = S * (1.0f / Dsz);
    const float var = Q * (1.0f / Dsz) - mu * mu;
    const float rstd = rsqrtf(var + 1e-5f);
    float4 g = *(const float4*)(gam + tid * 4);
    float4 b = *(const float4*)(bet + tid * 4);
    float4 o;
    o.x = (x.x - mu) * rstd * g.x + b.x;
    o.y = (x.y - mu) * rstd * g.y + b.y;
    o.z = (x.z - mu) * rstd * g.z + b.z;
    o.w = (x.w - mu) * rstd * g.w + b.w;
    *(float4*)(Y + (size_t)row * Dsz + tid * 4) = o;
}

// ---------------- split-K SGEMM: C_part[ks] = A[512,1024] * op(W[1024,1024]) -
// TRANS_B=1: C[m,n] = sum_k A[m,k] * W[n,k]   (x @ w.T)
// TRANS_B=0: C[m,n] = sum_k A[m,k] * W[k,n]   (x @ w)
// 128x128 tile, BK=16, 256 threads, 8x8 micro-tile, grid (4, 8, SPLITK).
template <int TRANS_B>
__global__ __launch_bounds__(256, 2) void gemm_k(const float* __restrict__ A,
                                                 const float* __restrict__ W,
                                                 float* __restrict__ P) {
    const int K = Dsz, N = Dsz;
    const int BM = 128, BN = 128, BK = 16;
    const int KC = K / SPLITK;  // 128
    __shared__ __align__(16) float As[BK][BM];
    __shared__ __align__(16) float Bs[BK][BN];
    const int bm = blockIdx.x, bn = blockIdx.y, ks = blockIdx.z;
    const int tid = threadIdx.x;
    const int tx = tid & 15, ty = tid >> 4;
    float acc[8][8];
#pragma unroll
    for (int i = 0; i < 8; ++i)
#pragma unroll
        for (int j = 0; j < 8; ++j) acc[i][j] = 0.f;

    const int k0 = ks * KC;
    for (int kt = 0; kt < KC; kt += BK) {
        const int kb = k0 + kt;
        // A tile [128 x 16], float4 along k, transpose into As[k][m]
#pragma unroll
        for (int L = 0; L < 2; ++L) {
            int f = tid + L * 256;
            int r = f >> 2, c4 = (f & 3) * 4;
            float4 v = *(const float4*)(A + (size_t)(bm * BM + r) * K + kb + c4);
            As[c4 + 0][r] = v.x; As[c4 + 1][r] = v.y;
            As[c4 + 2][r] = v.z; As[c4 + 3][r] = v.w;
        }
        if (TRANS_B) {
            // W[n,k] tile [128 x 16] -> Bs[k][n]
#pragma unroll
            for (int L = 0; L < 2; ++L) {
                int f = tid + L * 256;
                int r = f >> 2, c4 = (f & 3) * 4;
                float4 v = *(const float4*)(W + (size_t)(bn * BN + r) * K + kb + c4);
                Bs[c4 + 0][r] = v.x; Bs[c4 + 1][r] = v.y;
                Bs[c4 + 2][r] = v.z; Bs[c4 + 3][r] = v.w;
            }
        } else {
            // W[k,n] tile [16 x 128] -> Bs[k][n] directly (vector stores)
#pragma unroll
            for (int L = 0; L < 2; ++L) {
                int f = tid + L * 256;
                int r = f >> 5, c4 = (f & 31) * 4;
                float4 v = *(const float4*)(W + (size_t)(kb + r) * N + bn * BN + c4);
                *(float4*)&Bs[r][c4] = v;
            }
        }
        __syncthreads();
#pragma unroll
        for (int kk = 0; kk < BK; ++kk) {
            float a[8], b[8];
            float4 t;
            t = *(const float4*)&As[kk][ty * 8];     a[0]=t.x; a[1]=t.y; a[2]=t.z; a[3]=t.w;
            t = *(const float4*)&As[kk][ty * 8 + 4]; a[4]=t.x; a[5]=t.y; a[6]=t.z; a[7]=t.w;
            t = *(const float4*)&Bs[kk][tx * 8];     b[0]=t.x; b[1]=t.y; b[2]=t.z; b[3]=t.w;
            t = *(const float4*)&Bs[kk][tx * 8 + 4]; b[4]=t.x; b[5]=t.y; b[6]=t.z; b[7]=t.w;
#pragma unroll
            for (int i = 0; i < 8; ++i)
#pragma unroll
                for (int j = 0; j < 8; ++j) acc[i][j] += a[i] * b[j];
        }
        __syncthreads();
    }
    float* Pp = P + (size_t)ks * MN;
#pragma unroll
    for (int i = 0; i < 8; ++i) {
        const int m = bm * BM + ty * 8 + i;
        float* row = Pp + (size_t)m * N + bn * BN + tx * 8;
        *(float4*)(row + 0) = make_float4(acc[i][0], acc[i][1], acc[i][2], acc[i][3]);
        *(float4*)(row + 4) = make_float4(acc[i][4], acc[i][5], acc[i][6], acc[i][7]);
    }
}

// ---------------- combine split-K partials + bias (+ optional residual A) ---
template <bool HAS_BIAS, bool ADD_A>
__global__ __launch_bounds__(256) void combine_k(const float* __restrict__ P,
                                                 const float* __restrict__ bias,
                                                 const float* __restrict__ Aadd,
                                                 float* __restrict__ out) {
    const int idx = blockIdx.x * 256 + threadIdx.x;  // float4 index
    float4 s = make_float4(0.f, 0.f, 0.f, 0.f);
#pragma unroll
    for (int sl = 0; sl < SPLITK; ++sl) {
        float4 v = ((const float4*)(P + (size_t)sl * MN))[idx];
        s.x += v.x; s.y += v.y; s.z += v.z; s.w += v.w;
    }
    if (HAS_BIAS) {
        const int n = (idx * 4) & (Dsz - 1);
        float4 bv = *(const float4*)(bias + n);
        s.x += bv.x; s.y += bv.y; s.z += bv.z; s.w += bv.w;
    }
    if (ADD_A) {
        float4 av = ((const float4*)Aadd)[idx];
        s.x += av.x; s.y += av.y; s.z += av.z; s.w += av.w;
    }
    ((float4*)out)[idx] = s;
}

// ---------------- cb[b] = q[b] . k_b ----------------------------------------
__global__ __launch_bounds__(256) void cb_k(const float* __restrict__ q,
                                            const float* __restrict__ kb,
                                            float* __restrict__ cb) {
    __shared__ float red[8];
    const int b = blockIdx.x, tid = threadIdx.x;
    const int lane = tid & 31, w = tid >> 5;
    float4 a = *(const float4*)(q + (size_t)b * Dsz + tid * 4);
    float4 c = *(const float4*)(kb + tid * 4);
    float p = a.x * c.x + a.y * c.y + a.z * c.z + a.w * c.w;
#pragma unroll
    for (int o = 16; o; o >>= 1) p += __shfl_xor_sync(0xffffffffu, p, o);
    if (lane == 0) red[w] = p;
    __syncthreads();
    if (tid == 0) {
        float s = 0.f;
#pragma unroll
        for (int i = 0; i < 8; ++i) s += red[i];
        cb[b] = s;
    }
}

// ---------------- fused: LN1(video) + logits + online softmax + weighted sum
// One CTA per batch b. 256 threads, 4 d-lanes each. Reads video exactly once.
// s_out[b,d] = sum_f softmax_f((qp[b].ln(vf[b,f]) + cb[b]) / 32) * ln(vf[b,f])[d]
__global__ __launch_bounds__(256) void attn_fused(const float* __restrict__ video,
                                                  const float* __restrict__ qp,
                                                  const float* __restrict__ cbv,
                                                  const float* __restrict__ gam,
                                                  const float* __restrict__ bet,
                                                  float* __restrict__ s_out) {
    __shared__ float red[2][3][8];
    const int b = blockIdx.x, tid = threadIdx.x;
    const int lane = tid & 31, w = tid >> 5;
    const int d0 = tid * 4;
    float4 g4 = *(const float4*)(gam + d0);
    float4 b4 = *(const float4*)(bet + d0);
    float4 q4 = *(const float4*)(qp + (size_t)b * Dsz + d0);
    const float cbb = cbv[b];
    const float* base = video + (size_t)b * Fsz * Dsz;

    float m = -1e30f, l = 0.f;
    float4 acc = make_float4(0.f, 0.f, 0.f, 0.f);
    float4 x = *(const float4*)(base + d0);

    for (int f = 0; f < Fsz; ++f) {
        float4 xn = x;
        if (f + 1 < Fsz) xn = *(const float4*)(base + (size_t)(f + 1) * Dsz + d0);
        const int p = f & 1;
        // --- LN stats ---
        float ps = x.x + x.y + x.z + x.w;
        float pq = x.x * x.x + x.y * x.y + x.z * x.z + x.w * x.w;
#pragma unroll
        for (int o = 16; o; o >>= 1) {
            ps += __shfl_xor_sync(0xffffffffu, ps, o);
            pq += __shfl_xor_sync(0xffffffffu, pq, o);
        }
        if (lane == 0) { red[p][0][w] = ps; red[p][1][w] = pq; }
        __syncthreads();
        float S = 0.f, Q = 0.f;
#pragma unroll
        for (int i = 0; i < 8; ++i) { S += red[p][0][i]; Q += red[p][1][i]; }
        const float mu = S * (1.0f / Dsz);
        const float var = Q * (1.0f / Dsz) - mu * mu;
        const float rstd = rsqrtf(var + 1e-5f);
        float4 ln;
        ln.x = (x.x - mu) * rstd * g4.x + b4.x;
        ln.y = (x.y - mu) * rstd * g4.y + b4.y;
        ln.z = (x.z - mu) * rstd * g4.z + b4.z;
        ln.w = (x.w - mu) * rstd * g4.w + b4.w;
        // --- logit = (qp . ln + cb) / sqrt(D) ---
        float pd = ln.x * q4.x + ln.y * q4.y + ln.z * q4.z + ln.w * q4.w;
#pragma unroll
        for (int o = 16; o; o >>= 1) pd += __shfl_xor_sync(0xffffffffu, pd, o);
        if (lane == 0) red[p][2][w] = pd;
        __syncthreads();
        float dot = 0.f;
#pragma unroll
        for (int i = 0; i < 8; ++i) dot += red[p][2][i];
        const float logit = (dot + cbb) * 0.03125f;
        // --- online softmax update (uniform across all threads) ---
        const float mn = fmaxf(m, logit);
        const float alpha = __expf(m - mn);
        const float pw = __expf(logit - mn);
        l = l * alpha + pw;
        acc.x = acc.x * alpha + pw * ln.x;
        acc.y = acc.y * alpha + pw * ln.y;
        acc.z = acc.z * alpha + pw * ln.z;
        acc.w = acc.w * alpha + pw * ln.w;
        m = mn;
        x = xn;
    }
    const float inv = 1.0f / l;
    float4 o = make_float4(acc.x * inv, acc.y * inv, acc.z * inv, acc.w * inv);
    *(float4*)(s_out + (size_t)b * Dsz + d0) = o;
}

// ---------------- driver -----------------------------------------------------
extern "C" void kernel_launch(void* const* d_in, const int* in_sizes, int n_in,
                              void* d_out, int out_size) {
    (void)in_sizes; (void)n_in; (void)out_size;
    const float* text    = (const float*)d_in[0];
    const float* video   = (const float*)d_in[1];
    const float* q_w     = (const float*)d_in[2];
    const float* k_w     = (const float*)d_in[3];
    const float* v_w     = (const float*)d_in[4];
    const float* out_w   = (const float*)d_in[5];
    const float* lin_w   = (const float*)d_in[6];
    const float* q_b     = (const float*)d_in[7];
    const float* k_b     = (const float*)d_in[8];
    const float* v_b     = (const float*)d_in[9];
    const float* out_b   = (const float*)d_in[10];
    const float* lin_b   = (const float*)d_in[11];
    const float* ln1_g   = (const float*)d_in[12];
    const float* ln1_b   = (const float*)d_in[13];
    const float* ln2_g   = (const float*)d_in[14];
    const float* ln2_b   = (const float*)d_in[15];
    const float* ln3_g   = (const float*)d_in[16];
    const float* ln3_b   = (const float*)d_in[17];
    float* out = (float*)d_out;

    float *tln, *q, *qp, *cb, *s, *attn, *y, *aln, *z, *part;
    cudaGetSymbolAddress((void**)&tln,  g_tln);
    cudaGetSymbolAddress((void**)&q,    g_q);
    cudaGetSymbolAddress((void**)&qp,   g_qp);
    cudaGetSymbolAddress((void**)&cb,   g_cb);
    cudaGetSymbolAddress((void**)&s,    g_s);
    cudaGetSymbolAddress((void**)&attn, g_attn);
    cudaGetSymbolAddress((void**)&y,    g_y);
    cudaGetSymbolAddress((void**)&aln,  g_aln);
    cudaGetSymbolAddress((void**)&z,    g_z);
    cudaGetSymbolAddress((void**)&part, g_part);

    const dim3 gg(4, 8, SPLITK);
    const int cgrid = MN / 4 / 256;  // 512

    // t_ln = LN1(text)
    ln_rows<<<Bsz, 256>>>(text, tln, ln1_g, ln1_b);
    // q = t_ln @ q_w.T + q_b
    gemm_k<1><<<gg, 256>>>(tln, q_w, part);
    combine_k<true, false><<<cgrid, 256>>>(part, q_b, nullptr, q);
    // qp = q @ k_w  (k_w folded into query side)
    gemm_k<0><<<gg, 256>>>(q, k_w, part);
    combine_k<false, false><<<cgrid, 256>>>(part, nullptr, nullptr, qp);
    // cb[b] = q[b] . k_b
    cb_k<<<Bsz, 256>>>(q, k_b, cb);
    // s[b,:] = softmax-weighted sum of LN1(video[b,f,:])  (video read ONCE)
    attn_fused<<<Bsz, 256>>>(video, qp, cb, ln1_g, ln1_b, s);
    // attn = s @ v_w.T + v_b   (v_w folded after attention reduction)
    gemm_k<1><<<gg, 256>>>(s, v_w, part);
    combine_k<true, false><<<cgrid, 256>>>(part, v_b, nullptr, attn);
    // y = attn @ out_w.T + out_b
    gemm_k<1><<<gg, 256>>>(attn, out_w, part);
    combine_k<true, false><<<cgrid, 256>>>(part, out_b, nullptr, y);
    // a_ln = LN2(y)
    ln_rows<<<Bsz, 256>>>(y, aln, ln2_g, ln2_b);
    // z = a_ln + a_ln @ lin_w.T + lin_b
    gemm_k<1><<<gg, 256>>>(aln, lin_w, part);
    combine_k<true, true><<<cgrid, 256>>>(part, lin_b, aln, z);
    // out = LN3(z)
    ln_rows<<<Bsz, 256>>>(z, out, ln3_g, ln3_b);
}

// round 9
// speedup vs baseline: 1.3755x; 1.3755x over previous
#include <cuda_runtime.h>
#include <math.h>
#include <stdint.h>

#define Bsz 512
#define Fsz 128
#define Dsz 1024
#define MN (Bsz * Dsz)
#define TSPLIT 4

// ---------------- scratch (no allocs allowed -> __device__ globals) ----------
__device__ float g_tln[MN];
__device__ float g_q[MN];
__device__ float g_qp[MN];
__device__ float g_cb[Bsz];
__device__ float g_s[MN];
__device__ float g_attn[MN];
__device__ float g_y[MN];
__device__ float g_aln[MN];
__device__ float g_z[MN];
__device__ float g_part[(size_t)TSPLIT * MN];

// ---------------- helpers ----------------------------------------------------
__device__ __forceinline__ uint32_t f2tf(float x) {
    uint32_t u; asm("cvt.rna.tf32.f32 %0, %1;" : "=r"(u) : "f"(x)); return u;
}
__device__ __forceinline__ void mma8(float* c, const uint32_t* a, const uint32_t* b) {
    asm volatile(
        "mma.sync.aligned.m16n8k8.row.col.f32.tf32.tf32.f32 "
        "{%0,%1,%2,%3}, {%4,%5,%6,%7}, {%8,%9}, {%0,%1,%2,%3};"
        : "+f"(c[0]), "+f"(c[1]), "+f"(c[2]), "+f"(c[3])
        : "r"(a[0]), "r"(a[1]), "r"(a[2]), "r"(a[3]), "r"(b[0]), "r"(b[1]));
}

// ---------------- row LayerNorm over D=1024, 256 threads, float4/thread -----
__global__ __launch_bounds__(256) void ln_rows(const float* __restrict__ X,
                                               float* __restrict__ Y,
                                               const float* __restrict__ gam,
                                               const float* __restrict__ bet) {
    __shared__ float red[2][8];
    const int row = blockIdx.x, tid = threadIdx.x;
    const int lane = tid & 31, w = tid >> 5;
    const float* xr = X + (size_t)row * Dsz;
    float4 x = *(const float4*)(xr + tid * 4);
    float ps = x.x + x.y + x.z + x.w;
    float pq = x.x * x.x + x.y * x.y + x.z * x.z + x.w * x.w;
#pragma unroll
    for (int o = 16; o; o >>= 1) {
        ps += __shfl_xor_sync(0xffffffffu, ps, o);
        pq += __shfl_xor_sync(0xffffffffu, pq, o);
    }
    if (lane == 0) { red[0][w] = ps; red[1][w] = pq; }
    __syncthreads();
    float S = 0.f, Q = 0.f;
#pragma unroll
    for (int i = 0; i < 8; ++i) { S += red[0][i]; Q += red[1][i]; }
    const float mu = S * (1.0f / Dsz);
    const float var = Q * (1.0f / Dsz) - mu * mu;
    const float rstd = rsqrtf(var + 1e-5f);
    float4 g = *(const float4*)(gam + tid * 4);
    float4 b = *(const float4*)(bet + tid * 4);
    float4 o;
    o.x = (x.x - mu) * rstd * g.x + b.x;
    o.y = (x.y - mu) * rstd * g.y + b.y;
    o.z = (x.z - mu) * rstd * g.z + b.z;
    o.w = (x.w - mu) * rstd * g.w + b.w;
    *(float4*)(Y + (size_t)row * Dsz + tid * 4) = o;
}

// ---------------- mma.sync tf32 (3xTF32) split-K GEMM -----------------------
// C[m,n] = sum_k A[m,k] * (TRANS_B ? W[n,k] : W[k,n]); tile 128x128, BK=32,
// split-K=4 (grid z), 256 thr (8 warps, 64x32 warp-tiles), double-buffered.
// SMEM layout per stage (floats): Ahi[128][36], Alo[128][36],
//   Bhi, Blo: TRANS_B ? [128][36] : [32][132]  (both fit in 4608 floats).
#define STG 18432                   // floats per stage
#define AHI(s) ((s) * STG + 0)
#define ALO(s) ((s) * STG + 4608)
#define BHI(s) ((s) * STG + 9216)
#define BLO(s) ((s) * STG + 13824)
#define GM_SMEM (2 * STG * 4)       // 147456 bytes

template <int TRANS_B>
__global__ __launch_bounds__(256) void gemm_m(const float* __restrict__ A,
                                              const float* __restrict__ W,
                                              float* __restrict__ P) {
    extern __shared__ float sm[];
    const int tid = threadIdx.x, lane = tid & 31, wid = tid >> 5;
    const int bm = blockIdx.x, bn = blockIdx.y, ks = blockIdx.z;
    const int kbase = ks * (Dsz / TSPLIT);  // 256 K per CTA, 8 iters of 32
    const int g = lane >> 2, t4 = lane & 3;
    const int wm = (wid & 1) * 64, wn = (wid >> 1) * 32;

    float acc[4][4][4];
#pragma unroll
    for (int mi = 0; mi < 4; ++mi)
#pragma unroll
        for (int ni = 0; ni < 4; ++ni)
#pragma unroll
            for (int r = 0; r < 4; ++r) acc[mi][ni][r] = 0.f;

    float4 pa[4], pb[4];

    // ---- prefetch iter 0 ----
    {
        const int kb = kbase;
#pragma unroll
        for (int L = 0; L < 4; ++L) {
            const int f = tid + L * 256, r = f >> 3, c4 = (f & 7) * 4;
            pa[L] = *(const float4*)(A + (size_t)(bm * 128 + r) * Dsz + kb + c4);
        }
        if (TRANS_B) {
#pragma unroll
            for (int L = 0; L < 4; ++L) {
                const int f = tid + L * 256, r = f >> 3, c4 = (f & 7) * 4;
                pb[L] = *(const float4*)(W + (size_t)(bn * 128 + r) * Dsz + kb + c4);
            }
        } else {
#pragma unroll
            for (int L = 0; L < 4; ++L) {
                const int f = tid + L * 256, kk = f >> 5, n4 = (f & 31) * 4;
                pb[L] = *(const float4*)(W + (size_t)(kb + kk) * Dsz + bn * 128 + n4);
            }
        }
    }
    // ---- store stage 0 ----
#pragma unroll
    for (int L = 0; L < 4; ++L) {
        const int f = tid + L * 256, r = f >> 3, c4 = (f & 7) * 4;
        float4 v = pa[L];
        uint4 h = make_uint4(f2tf(v.x), f2tf(v.y), f2tf(v.z), f2tf(v.w));
        uint4 l = make_uint4(f2tf(v.x - __uint_as_float(h.x)),
                             f2tf(v.y - __uint_as_float(h.y)),
                             f2tf(v.z - __uint_as_float(h.z)),
                             f2tf(v.w - __uint_as_float(h.w)));
        *(uint4*)(sm + AHI(0) + r * 36 + c4) = h;
        *(uint4*)(sm + ALO(0) + r * 36 + c4) = l;
    }
#pragma unroll
    for (int L = 0; L < 4; ++L) {
        const int f = tid + L * 256;
        const int off = TRANS_B ? ((f >> 3) * 36 + (f & 7) * 4)
                                : ((f >> 5) * 132 + (f & 31) * 4);
        float4 v = pb[L];
        uint4 h = make_uint4(f2tf(v.x), f2tf(v.y), f2tf(v.z), f2tf(v.w));
        uint4 l = make_uint4(f2tf(v.x - __uint_as_float(h.x)),
                             f2tf(v.y - __uint_as_float(h.y)),
                             f2tf(v.z - __uint_as_float(h.z)),
                             f2tf(v.w - __uint_as_float(h.w)));
        *(uint4*)(sm + BHI(0) + off) = h;
        *(uint4*)(sm + BLO(0) + off) = l;
    }
    __syncthreads();

    for (int it = 0; it < 8; ++it) {
        const int s = it & 1;
        // ---- prefetch next tile (overlaps MMA below) ----
        if (it + 1 < 8) {
            const int kb = kbase + (it + 1) * 32;
#pragma unroll
            for (int L = 0; L < 4; ++L) {
                const int f = tid + L * 256, r = f >> 3, c4 = (f & 7) * 4;
                pa[L] = *(const float4*)(A + (size_t)(bm * 128 + r) * Dsz + kb + c4);
            }
            if (TRANS_B) {
#pragma unroll
                for (int L = 0; L < 4; ++L) {
                    const int f = tid + L * 256, r = f >> 3, c4 = (f & 7) * 4;
                    pb[L] = *(const float4*)(W + (size_t)(bn * 128 + r) * Dsz + kb + c4);
                }
            } else {
#pragma unroll
                for (int L = 0; L < 4; ++L) {
                    const int f = tid + L * 256, kk = f >> 5, n4 = (f & 31) * 4;
                    pb[L] = *(const float4*)(W + (size_t)(kb + kk) * Dsz + bn * 128 + n4);
                }
            }
        }
        // ---- compute stage s ----
        const float* Ah = sm + AHI(s);
        const float* Al = sm + ALO(s);
        const float* Bh = sm + BHI(s);
        const float* Bl = sm + BLO(s);
#pragma unroll
        for (int kq = 0; kq < 4; ++kq) {
            const int k0 = kq * 8;
            uint32_t ah[4][4], al[4][4];
#pragma unroll
            for (int mi = 0; mi < 4; ++mi) {
                const int b0 = (wm + mi * 16 + g) * 36 + k0 + t4;
                const int b1 = b0 + 8 * 36;
                ah[mi][0] = __float_as_uint(Ah[b0]);
                ah[mi][1] = __float_as_uint(Ah[b1]);
                ah[mi][2] = __float_as_uint(Ah[b0 + 4]);
                ah[mi][3] = __float_as_uint(Ah[b1 + 4]);
                al[mi][0] = __float_as_uint(Al[b0]);
                al[mi][1] = __float_as_uint(Al[b1]);
                al[mi][2] = __float_as_uint(Al[b0 + 4]);
                al[mi][3] = __float_as_uint(Al[b1 + 4]);
            }
            uint32_t bh[4][2], bl[4][2];
#pragma unroll
            for (int ni = 0; ni < 4; ++ni) {
                int i0, i1;
                if (TRANS_B) {
                    i0 = (wn + ni * 8 + g) * 36 + k0 + t4;
                    i1 = i0 + 4;
                } else {
                    i0 = (k0 + t4) * 132 + wn + ni * 8 + g;
                    i1 = i0 + 4 * 132;
                }
                bh[ni][0] = __float_as_uint(Bh[i0]);
                bh[ni][1] = __float_as_uint(Bh[i1]);
                bl[ni][0] = __float_as_uint(Bl[i0]);
                bl[ni][1] = __float_as_uint(Bl[i1]);
            }
#pragma unroll
            for (int mi = 0; mi < 4; ++mi)
#pragma unroll
                for (int ni = 0; ni < 4; ++ni) {
                    mma8(acc[mi][ni], ah[mi], bh[ni]);
                    mma8(acc[mi][ni], al[mi], bh[ni]);
                    mma8(acc[mi][ni], ah[mi], bl[ni]);
                }
        }
        // ---- store next stage ----
        if (it + 1 < 8) {
            const int ns = (it + 1) & 1;
#pragma unroll
            for (int L = 0; L < 4; ++L) {
                const int f = tid + L * 256, r = f >> 3, c4 = (f & 7) * 4;
                float4 v = pa[L];
                uint4 h = make_uint4(f2tf(v.x), f2tf(v.y), f2tf(v.z), f2tf(v.w));
                uint4 l = make_uint4(f2tf(v.x - __uint_as_float(h.x)),
                                     f2tf(v.y - __uint_as_float(h.y)),
                                     f2tf(v.z - __uint_as_float(h.z)),
                                     f2tf(v.w - __uint_as_float(h.w)));
                *(uint4*)(sm + AHI(ns) + r * 36 + c4) = h;
                *(uint4*)(sm + ALO(ns) + r * 36 + c4) = l;
            }
#pragma unroll
            for (int L = 0; L < 4; ++L) {
                const int f = tid + L * 256;
                const int off = TRANS_B ? ((f >> 3) * 36 + (f & 7) * 4)
                                        : ((f >> 5) * 132 + (f & 31) * 4);
                float4 v = pb[L];
                uint4 h = make_uint4(f2tf(v.x), f2tf(v.y), f2tf(v.z), f2tf(v.w));
                uint4 l = make_uint4(f2tf(v.x - __uint_as_float(h.x)),
                                     f2tf(v.y - __uint_as_float(h.y)),
                                     f2tf(v.z - __uint_as_float(h.z)),
                                     f2tf(v.w - __uint_as_float(h.w)));
                *(uint4*)(sm + BHI(ns) + off) = h;
                *(uint4*)(sm + BLO(ns) + off) = l;
            }
        }
        __syncthreads();
    }

    // ---- epilogue: write partials ----
    float* Pp = P + (size_t)ks * MN;
#pragma unroll
    for (int mi = 0; mi < 4; ++mi) {
        const int m0 = bm * 128 + wm + mi * 16 + g;
#pragma unroll
        for (int ni = 0; ni < 4; ++ni) {
            const int n = bn * 128 + wn + ni * 8 + 2 * t4;
            *(float2*)(Pp + (size_t)m0 * Dsz + n) =
                make_float2(acc[mi][ni][0], acc[mi][ni][1]);
            *(float2*)(Pp + (size_t)(m0 + 8) * Dsz + n) =
                make_float2(acc[mi][ni][2], acc[mi][ni][3]);
        }
    }
}

// ---------------- combine split-K partials + bias (+ optional residual A) ---
template <bool HAS_BIAS, bool ADD_A>
__global__ __launch_bounds__(256) void combine_k(const float* __restrict__ P,
                                                 const float* __restrict__ bias,
                                                 const float* __restrict__ Aadd,
                                                 float* __restrict__ out) {
    const int idx = blockIdx.x * 256 + threadIdx.x;  // float4 index
    float4 s = make_float4(0.f, 0.f, 0.f, 0.f);
#pragma unroll
    for (int sl = 0; sl < TSPLIT; ++sl) {
        float4 v = ((const float4*)(P + (size_t)sl * MN))[idx];
        s.x += v.x; s.y += v.y; s.z += v.z; s.w += v.w;
    }
    if (HAS_BIAS) {
        const int n = (idx * 4) & (Dsz - 1);
        float4 bv = *(const float4*)(bias + n);
        s.x += bv.x; s.y += bv.y; s.z += bv.z; s.w += bv.w;
    }
    if (ADD_A) {
        float4 av = ((const float4*)Aadd)[idx];
        s.x += av.x; s.y += av.y; s.z += av.z; s.w += av.w;
    }
    ((float4*)out)[idx] = s;
}

// ---------------- cb[b] = q[b] . k_b ----------------------------------------
__global__ __launch_bounds__(256) void cb_k(const float* __restrict__ q,
                                            const float* __restrict__ kb,
                                            float* __restrict__ cb) {
    __shared__ float red[8];
    const int b = blockIdx.x, tid = threadIdx.x;
    const int lane = tid & 31, w = tid >> 5;
    float4 a = *(const float4*)(q + (size_t)b * Dsz + tid * 4);
    float4 c = *(const float4*)(kb + tid * 4);
    float p = a.x * c.x + a.y * c.y + a.z * c.z + a.w * c.w;
#pragma unroll
    for (int o = 16; o; o >>= 1) p += __shfl_xor_sync(0xffffffffu, p, o);
    if (lane == 0) red[w] = p;
    __syncthreads();
    if (tid == 0) {
        float s = 0.f;
#pragma unroll
        for (int i = 0; i < 8; ++i) s += red[i];
        cb[b] = s;
    }
}

// ---------------- fused attention: 2 frames/iteration (1 barrier per frame) -
__global__ __launch_bounds__(256) void attn_fused(const float* __restrict__ video,
                                                  const float* __restrict__ qp,
                                                  const float* __restrict__ cbv,
                                                  const float* __restrict__ gam,
                                                  const float* __restrict__ bet,
                                                  float* __restrict__ s_out) {
    __shared__ float red[2][6][8];
    const int b = blockIdx.x, tid = threadIdx.x;
    const int lane = tid & 31, w = tid >> 5;
    const int d0 = tid * 4;
    float4 g4 = *(const float4*)(gam + d0);
    float4 b4 = *(const float4*)(bet + d0);
    float4 q4 = *(const float4*)(qp + (size_t)b * Dsz + d0);
    const float cbb = cbv[b];
    const float* base = video + (size_t)b * Fsz * Dsz;

    float m = -1e30f, l = 0.f;
    float4 acc = make_float4(0.f, 0.f, 0.f, 0.f);
    float4 x0 = *(const float4*)(base + d0);
    float4 x1 = *(const float4*)(base + Dsz + d0);

    for (int f = 0; f < Fsz; f += 2) {
        float4 n0 = x0, n1 = x1;
        if (f + 2 < Fsz) {
            n0 = *(const float4*)(base + (size_t)(f + 2) * Dsz + d0);
            n1 = *(const float4*)(base + (size_t)(f + 3) * Dsz + d0);
        }
        const int p = (f >> 1) & 1;
        float s0 = x0.x + x0.y + x0.z + x0.w;
        float q0 = x0.x * x0.x + x0.y * x0.y + x0.z * x0.z + x0.w * x0.w;
        float s1 = x1.x + x1.y + x1.z + x1.w;
        float q1 = x1.x * x1.x + x1.y * x1.y + x1.z * x1.z + x1.w * x1.w;
#pragma unroll
        for (int o = 16; o; o >>= 1) {
            s0 += __shfl_xor_sync(0xffffffffu, s0, o);
            q0 += __shfl_xor_sync(0xffffffffu, q0, o);
            s1 += __shfl_xor_sync(0xffffffffu, s1, o);
            q1 += __shfl_xor_sync(0xffffffffu, q1, o);
        }
        if (lane == 0) {
            red[p][0][w] = s0; red[p][1][w] = q0;
            red[p][2][w] = s1; red[p][3][w] = q1;
        }
        __syncthreads();
        float S0 = 0.f, Q0 = 0.f, S1 = 0.f, Q1 = 0.f;
#pragma unroll
        for (int i = 0; i < 8; ++i) {
            S0 += red[p][0][i]; Q0 += red[p][1][i];
            S1 += red[p][2][i]; Q1 += red[p][3][i];
        }
        const float mu0 = S0 * (1.0f / Dsz);
        const float r0 = rsqrtf(Q0 * (1.0f / Dsz) - mu0 * mu0 + 1e-5f);
        const float mu1 = S1 * (1.0f / Dsz);
        const float r1 = rsqrtf(Q1 * (1.0f / Dsz) - mu1 * mu1 + 1e-5f);
        float4 ln0, ln1;
        ln0.x = (x0.x - mu0) * r0 * g4.x + b4.x;
        ln0.y = (x0.y - mu0) * r0 * g4.y + b4.y;
        ln0.z = (x0.z - mu0) * r0 * g4.z + b4.z;
        ln0.w = (x0.w - mu0) * r0 * g4.w + b4.w;
        ln1.x = (x1.x - mu1) * r1 * g4.x + b4.x;
        ln1.y = (x1.y - mu1) * r1 * g4.y + b4.y;
        ln1.z = (x1.z - mu1) * r1 * g4.z + b4.z;
        ln1.w = (x1.w - mu1) * r1 * g4.w + b4.w;
        float d0p = ln0.x * q4.x + ln0.y * q4.y + ln0.z * q4.z + ln0.w * q4.w;
        float d1p = ln1.x * q4.x + ln1.y * q4.y + ln1.z * q4.z + ln1.w * q4.w;
#pragma unroll
        for (int o = 16; o; o >>= 1) {
            d0p += __shfl_xor_sync(0xffffffffu, d0p, o);
            d1p += __shfl_xor_sync(0xffffffffu, d1p, o);
        }
        if (lane == 0) { red[p][4][w] = d0p; red[p][5][w] = d1p; }
        __syncthreads();
        float dt0 = 0.f, dt1 = 0.f;
#pragma unroll
        for (int i = 0; i < 8; ++i) { dt0 += red[p][4][i]; dt1 += red[p][5][i]; }
        const float lg0 = (dt0 + cbb) * 0.03125f;
        const float lg1 = (dt1 + cbb) * 0.03125f;
        const float mn = fmaxf(m, fmaxf(lg0, lg1));
        const float alpha = __expf(m - mn);
        const float p0 = __expf(lg0 - mn);
        const float p1 = __expf(lg1 - mn);
        l = l * alpha + p0 + p1;
        acc.x = acc.x * alpha + p0 * ln0.x + p1 * ln1.x;
        acc.y = acc.y * alpha + p0 * ln0.y + p1 * ln1.y;
        acc.z = acc.z * alpha + p0 * ln0.z + p1 * ln1.z;
        acc.w = acc.w * alpha + p0 * ln0.w + p1 * ln1.w;
        m = mn;
        x0 = n0; x1 = n1;
    }
    const float inv = 1.0f / l;
    *(float4*)(s_out + (size_t)b * Dsz + d0) =
        make_float4(acc.x * inv, acc.y * inv, acc.z * inv, acc.w * inv);
}

// ---------------- driver -----------------------------------------------------
extern "C" void kernel_launch(void* const* d_in, const int* in_sizes, int n_in,
                              void* d_out, int out_size) {
    (void)in_sizes; (void)n_in; (void)out_size;
    const float* text  = (const float*)d_in[0];
    const float* video = (const float*)d_in[1];
    const float* q_w   = (const float*)d_in[2];
    const float* k_w   = (const float*)d_in[3];
    const float* v_w   = (const float*)d_in[4];
    const float* out_w = (const float*)d_in[5];
    const float* lin_w = (const float*)d_in[6];
    const float* q_b   = (const float*)d_in[7];
    const float* k_b   = (const float*)d_in[8];
    const float* v_b   = (const float*)d_in[9];
    const float* out_b = (const float*)d_in[10];
    const float* lin_b = (const float*)d_in[11];
    const float* ln1_g = (const float*)d_in[12];
    const float* ln1_b = (const float*)d_in[13];
    const float* ln2_g = (const float*)d_in[14];
    const float* ln2_b = (const float*)d_in[15];
    const float* ln3_g = (const float*)d_in[16];
    const float* ln3_b = (const float*)d_in[17];
    float* out = (float*)d_out;

    float *tln, *q, *qp, *cb, *s, *attn, *y, *aln, *z, *part;
    cudaGetSymbolAddress((void**)&tln,  g_tln);
    cudaGetSymbolAddress((void**)&q,    g_q);
    cudaGetSymbolAddress((void**)&qp,   g_qp);
    cudaGetSymbolAddress((void**)&cb,   g_cb);
    cudaGetSymbolAddress((void**)&s,    g_s);
    cudaGetSymbolAddress((void**)&attn, g_attn);
    cudaGetSymbolAddress((void**)&y,    g_y);
    cudaGetSymbolAddress((void**)&aln,  g_aln);
    cudaGetSymbolAddress((void**)&z,    g_z);
    cudaGetSymbolAddress((void**)&part, g_part);

    cudaFuncSetAttribute(gemm_m<0>, cudaFuncAttributeMaxDynamicSharedMemorySize, GM_SMEM);
    cudaFuncSetAttribute(gemm_m<1>, cudaFuncAttributeMaxDynamicSharedMemorySize, GM_SMEM);

    const dim3 gg(4, 8, TSPLIT);
    const int cgrid = MN / 4 / 256;  // 512

    // t_ln = LN1(text)
    ln_rows<<<Bsz, 256>>>(text, tln, ln1_g, ln1_b);
    // q = t_ln @ q_w.T + q_b
    gemm_m<1><<<gg, 256, GM_SMEM>>>(tln, q_w, part);
    combine_k<true, false><<<cgrid, 256>>>(part, q_b, nullptr, q);
    // qp = q @ k_w  (k_w folded into query side)
    gemm_m<0><<<gg, 256, GM_SMEM>>>(q, k_w, part);
    combine_k<false, false><<<cgrid, 256>>>(part, nullptr, nullptr, qp);
    // cb[b] = q[b] . k_b
    cb_k<<<Bsz, 256>>>(q, k_b, cb);
    // s = softmax-weighted sum of LN1(video)  (video read once)
    attn_fused<<<Bsz, 256>>>(video, qp, cb, ln1_g, ln1_b, s);
    // attn = s @ v_w.T + v_b   (v_w folded after attention reduction)
    gemm_m<1><<<gg, 256, GM_SMEM>>>(s, v_w, part);
    combine_k<true, false><<<cgrid, 256>>>(part, v_b, nullptr, attn);
    // y = attn @ out_w.T + out_b
    gemm_m<1><<<gg, 256, GM_SMEM>>>(attn, out_w, part);
    combine_k<true, false><<<cgrid, 256>>>(part, out_b, nullptr, y);
    // a_ln = LN2(y)
    ln_rows<<<Bsz, 256>>>(y, aln, ln2_g, ln2_b);
    // z = a_ln + a_ln @ lin_w.T + lin_b
    gemm_m<1><<<gg, 256, GM_SMEM>>>(aln, lin_w, part);
    combine_k<true, true><<<cgrid, 256>>>(part, lin_b, aln, z);
    // out = LN3(z)
    ln_rows<<<Bsz, 256>>>(z, out, ln3_g, ln3_b);
}

// round 10
// speedup vs baseline: 1.7869x; 1.2991x over previous
#include <cuda_runtime.h>
#include <math.h>
#include <stdint.h>

#define Bsz 512
#define Fsz 128
#define Dsz 1024
#define MN (Bsz * Dsz)
#define TSPLIT 4

// ---------------- scratch (no allocs allowed -> __device__ globals) ----------
__device__ float g_tln[MN];
__device__ float g_q[MN];
__device__ float g_qp[MN];
__device__ float g_cb[Bsz];
__device__ float g_s[MN];
__device__ float g_attn[MN];
__device__ float g_y[MN];
__device__ float g_aln[MN];
__device__ float g_z[MN];
__device__ float g_part[(size_t)TSPLIT * MN];
__device__ float g_kwt[Dsz * Dsz];     // k_w transposed
__device__ float g_s2[2 * MN];         // attention chunk partials
__device__ float g_ml[Bsz * 4];        // per-chunk (m, l)

// ---------------- helpers ----------------------------------------------------
__device__ __forceinline__ void mma16(float* c, const uint32_t* a, const uint32_t* b) {
    asm volatile(
        "mma.sync.aligned.m16n8k16.row.col.f32.bf16.bf16.f32 "
        "{%0,%1,%2,%3}, {%4,%5,%6,%7}, {%8,%9}, {%0,%1,%2,%3};"
        : "+f"(c[0]), "+f"(c[1]), "+f"(c[2]), "+f"(c[3])
        : "r"(a[0]), "r"(a[1]), "r"(a[2]), "r"(a[3]), "r"(b[0]), "r"(b[1]));
}
// split float4 (4 consecutive k) into bf16x2 hi/lo plane words (k-pairs)
__device__ __forceinline__ void cvt_planes(float4 v, uint32_t& h0, uint32_t& h1,
                                           uint32_t& l0, uint32_t& l1) {
    const uint32_t bx = __float_as_uint(v.x), by = __float_as_uint(v.y);
    const uint32_t bz = __float_as_uint(v.z), bw = __float_as_uint(v.w);
    h0 = (by & 0xFFFF0000u) | (bx >> 16);
    h1 = (bw & 0xFFFF0000u) | (bz >> 16);
    const float lx = v.x - __uint_as_float(bx & 0xFFFF0000u);
    const float ly = v.y - __uint_as_float(by & 0xFFFF0000u);
    const float lz = v.z - __uint_as_float(bz & 0xFFFF0000u);
    const float lw = v.w - __uint_as_float(bw & 0xFFFF0000u);
    asm("cvt.rn.bf16x2.f32 %0, %1, %2;" : "=r"(l0) : "f"(ly), "f"(lx));
    asm("cvt.rn.bf16x2.f32 %0, %1, %2;" : "=r"(l1) : "f"(lw), "f"(lz));
}

// ---------------- 1024x1024 transpose (for k_w) ------------------------------
__global__ __launch_bounds__(256) void transp(const float* __restrict__ in,
                                              float* __restrict__ out) {
    __shared__ float t[32][33];
    int x = blockIdx.x * 32 + threadIdx.x;
    int y = blockIdx.y * 32 + threadIdx.y;
#pragma unroll
    for (int j = 0; j < 32; j += 8) t[threadIdx.y + j][threadIdx.x] = in[(size_t)(y + j) * Dsz + x];
    __syncthreads();
    x = blockIdx.y * 32 + threadIdx.x;
    y = blockIdx.x * 32 + threadIdx.y;
#pragma unroll
    for (int j = 0; j < 32; j += 8) out[(size_t)(y + j) * Dsz + x] = t[threadIdx.x][threadIdx.y + j];
}

// ---------------- row LayerNorm over D=1024, 256 threads, float4/thread -----
__global__ __launch_bounds__(256) void ln_rows(const float* __restrict__ X,
                                               float* __restrict__ Y,
                                               const float* __restrict__ gam,
                                               const float* __restrict__ bet) {
    __shared__ float red[2][8];
    const int row = blockIdx.x, tid = threadIdx.x;
    const int lane = tid & 31, w = tid >> 5;
    const float* xr = X + (size_t)row * Dsz;
    float4 x = *(const float4*)(xr + tid * 4);
    float ps = x.x + x.y + x.z + x.w;
    float pq = x.x * x.x + x.y * x.y + x.z * x.z + x.w * x.w;
#pragma unroll
    for (int o = 16; o; o >>= 1) {
        ps += __shfl_xor_sync(0xffffffffu, ps, o);
        pq += __shfl_xor_sync(0xffffffffu, pq, o);
    }
    if (lane == 0) { red[0][w] = ps; red[1][w] = pq; }
    __syncthreads();
    float S = 0.f, Q = 0.f;
#pragma unroll
    for (int i = 0; i < 8; ++i) { S += red[0][i]; Q += red[1][i]; }
    const float mu = S * (1.0f / Dsz);
    const float var = Q * (1.0f / Dsz) - mu * mu;
    const float rstd = rsqrtf(var + 1e-5f);
    float4 g = *(const float4*)(gam + tid * 4);
    float4 b = *(const float4*)(bet + tid * 4);
    float4 o;
    o.x = (x.x - mu) * rstd * g.x + b.x;
    o.y = (x.y - mu) * rstd * g.y + b.y;
    o.z = (x.z - mu) * rstd * g.z + b.z;
    o.w = (x.w - mu) * rstd * g.w + b.w;
    *(float4*)(Y + (size_t)row * Dsz + tid * 4) = o;
}

// ---------------- mma.sync bf16-split (3 terms) split-K GEMM ----------------
// C[m,n] = sum_k A[m,k] * W[n,k]  (W K-major). Tile 128x128, BK=32, split-K=4,
// 256 thr (8 warps, 64x32 warp-tiles), double-buffered SMEM.
// Planes: uint32 (bf16x2 k-pairs) [128 rows][NP=20 words]; 2560 words/plane.
#define NP 20
#define PLW 2560
#define AH(s) ((s) * 10240 + 0)
#define AL(s) ((s) * 10240 + 2560)
#define BH(s) ((s) * 10240 + 5120)
#define BL(s) ((s) * 10240 + 7680)
#define GM_SMEM (2 * 10240 * 4)  // 81920 B

__global__ __launch_bounds__(256) void gemm_m(const float* __restrict__ A,
                                              const float* __restrict__ W,
                                              float* __restrict__ P) {
    extern __shared__ uint32_t sm[];
    const int tid = threadIdx.x, lane = tid & 31, wid = tid >> 5;
    const int bm = blockIdx.x, bn = blockIdx.y, ks = blockIdx.z;
    const int kbase = ks * (Dsz / TSPLIT);  // 256 K per CTA, 8 iters of 32
    const int g = lane >> 2, t4 = lane & 3;
    const int wm = (wid & 1) * 64, wn = (wid >> 1) * 32;

    float acc[4][4][4];
#pragma unroll
    for (int mi = 0; mi < 4; ++mi)
#pragma unroll
        for (int ni = 0; ni < 4; ++ni)
#pragma unroll
            for (int r = 0; r < 4; ++r) acc[mi][ni][r] = 0.f;

    float4 pa[4], pb[4];
    const int fr = tid >> 3, fj = tid & 7;       // row 0..31, k-quad 0..7
    const int pw = fj * 2;                        // pair-word offset 0..14

    // ---- prefetch iter 0 ----
#pragma unroll
    for (int L = 0; L < 4; ++L) {
        pa[L] = *(const float4*)(A + (size_t)(bm * 128 + fr + L * 32) * Dsz + kbase + fj * 4);
        pb[L] = *(const float4*)(W + (size_t)(bn * 128 + fr + L * 32) * Dsz + kbase + fj * 4);
    }
    // ---- store stage 0 ----
#pragma unroll
    for (int L = 0; L < 4; ++L) {
        uint32_t h0, h1, l0, l1;
        const int off = (fr + L * 32) * NP + pw;
        cvt_planes(pa[L], h0, h1, l0, l1);
        *(uint2*)(sm + AH(0) + off) = make_uint2(h0, h1);
        *(uint2*)(sm + AL(0) + off) = make_uint2(l0, l1);
        cvt_planes(pb[L], h0, h1, l0, l1);
        *(uint2*)(sm + BH(0) + off) = make_uint2(h0, h1);
        *(uint2*)(sm + BL(0) + off) = make_uint2(l0, l1);
    }
    __syncthreads();

    for (int it = 0; it < 8; ++it) {
        const int s = it & 1;
        if (it + 1 < 8) {
            const int kb = kbase + (it + 1) * 32;
#pragma unroll
            for (int L = 0; L < 4; ++L) {
                pa[L] = *(const float4*)(A + (size_t)(bm * 128 + fr + L * 32) * Dsz + kb + fj * 4);
                pb[L] = *(const float4*)(W + (size_t)(bn * 128 + fr + L * 32) * Dsz + kb + fj * 4);
            }
        }
        const uint32_t* Ah = sm + AH(s);
        const uint32_t* Al = sm + AL(s);
        const uint32_t* Bh = sm + BH(s);
        const uint32_t* Bl = sm + BL(s);
#pragma unroll
        for (int kq = 0; kq < 2; ++kq) {   // two k16 chunks per iter
            const int kp = kq * 8 + t4;
            uint32_t ah[4][4], al[4][4];
#pragma unroll
            for (int mi = 0; mi < 4; ++mi) {
                const int b0 = (wm + mi * 16 + g) * NP + kp;
                const int b1 = b0 + 8 * NP;
                ah[mi][0] = Ah[b0];     ah[mi][1] = Ah[b1];
                ah[mi][2] = Ah[b0 + 4]; ah[mi][3] = Ah[b1 + 4];
                al[mi][0] = Al[b0];     al[mi][1] = Al[b1];
                al[mi][2] = Al[b0 + 4]; al[mi][3] = Al[b1 + 4];
            }
            uint32_t bh[4][2], bl[4][2];
#pragma unroll
            for (int ni = 0; ni < 4; ++ni) {
                const int i0 = (wn + ni * 8 + g) * NP + kp;
                bh[ni][0] = Bh[i0]; bh[ni][1] = Bh[i0 + 4];
                bl[ni][0] = Bl[i0]; bl[ni][1] = Bl[i0 + 4];
            }
#pragma unroll
            for (int mi = 0; mi < 4; ++mi)
#pragma unroll
                for (int ni = 0; ni < 4; ++ni) {
                    mma16(acc[mi][ni], ah[mi], bh[ni]);
                    mma16(acc[mi][ni], al[mi], bh[ni]);
                    mma16(acc[mi][ni], ah[mi], bl[ni]);
                }
        }
        if (it + 1 < 8) {
            const int ns = (it + 1) & 1;
#pragma unroll
            for (int L = 0; L < 4; ++L) {
                uint32_t h0, h1, l0, l1;
                const int off = (fr + L * 32) * NP + pw;
                cvt_planes(pa[L], h0, h1, l0, l1);
                *(uint2*)(sm + AH(ns) + off) = make_uint2(h0, h1);
                *(uint2*)(sm + AL(ns) + off) = make_uint2(l0, l1);
                cvt_planes(pb[L], h0, h1, l0, l1);
                *(uint2*)(sm + BH(ns) + off) = make_uint2(h0, h1);
                *(uint2*)(sm + BL(ns) + off) = make_uint2(l0, l1);
            }
        }
        __syncthreads();
    }

    // ---- epilogue: write partials ----
    float* Pp = P + (size_t)ks * MN;
#pragma unroll
    for (int mi = 0; mi < 4; ++mi) {
        const int m0 = bm * 128 + wm + mi * 16 + g;
#pragma unroll
        for (int ni = 0; ni < 4; ++ni) {
            const int n = bn * 128 + wn + ni * 8 + 2 * t4;
            *(float2*)(Pp + (size_t)m0 * Dsz + n) =
                make_float2(acc[mi][ni][0], acc[mi][ni][1]);
            *(float2*)(Pp + (size_t)(m0 + 8) * Dsz + n) =
                make_float2(acc[mi][ni][2], acc[mi][ni][3]);
        }
    }
}

// ---------------- combine split-K partials + bias (+ optional residual A) ---
template <bool HAS_BIAS, bool ADD_A>
__global__ __launch_bounds__(256) void combine_k(const float* __restrict__ P,
                                                 const float* __restrict__ bias,
                                                 const float* __restrict__ Aadd,
                                                 float* __restrict__ out) {
    const int idx = blockIdx.x * 256 + threadIdx.x;  // float4 index
    float4 s = make_float4(0.f, 0.f, 0.f, 0.f);
#pragma unroll
    for (int sl = 0; sl < TSPLIT; ++sl) {
        float4 v = ((const float4*)(P + (size_t)sl * MN))[idx];
        s.x += v.x; s.y += v.y; s.z += v.z; s.w += v.w;
    }
    if (HAS_BIAS) {
        const int n = (idx * 4) & (Dsz - 1);
        float4 bv = *(const float4*)(bias + n);
        s.x += bv.x; s.y += bv.y; s.z += bv.z; s.w += bv.w;
    }
    if (ADD_A) {
        float4 av = ((const float4*)Aadd)[idx];
        s.x += av.x; s.y += av.y; s.z += av.z; s.w += av.w;
    }
    ((float4*)out)[idx] = s;
}

// ---------------- cb[b] = q[b] . k_b ----------------------------------------
__global__ __launch_bounds__(256) void cb_k(const float* __restrict__ q,
                                            const float* __restrict__ kb,
                                            float* __restrict__ cb) {
    __shared__ float red[8];
    const int b = blockIdx.x, tid = threadIdx.x;
    const int lane = tid & 31, w = tid >> 5;
    float4 a = *(const float4*)(q + (size_t)b * Dsz + tid * 4);
    float4 c = *(const float4*)(kb + tid * 4);
    float p = a.x * c.x + a.y * c.y + a.z * c.z + a.w * c.w;
#pragma unroll
    for (int o = 16; o; o >>= 1) p += __shfl_xor_sync(0xffffffffu, p, o);
    if (lane == 0) red[w] = p;
    __syncthreads();
    if (tid == 0) {
        float s = 0.f;
#pragma unroll
        for (int i = 0; i < 8; ++i) s += red[i];
        cb[b] = s;
    }
}

// ---------------- fused attention: 2 CTAs/batch, 2 frames/iteration ---------
// CTA (b, c) handles frames [c*64, c*64+64). Writes unnormalized acc + (m, l).
__global__ __launch_bounds__(256) void attn_fused(const float* __restrict__ video,
                                                  const float* __restrict__ qp,
                                                  const float* __restrict__ cbv,
                                                  const float* __restrict__ gam,
                                                  const float* __restrict__ bet,
                                                  float* __restrict__ s2,
                                                  float* __restrict__ ml) {
    __shared__ float red[2][6][8];
    const int b = blockIdx.x, chunk = blockIdx.y, tid = threadIdx.x;
    const int lane = tid & 31, w = tid >> 5;
    const int d0 = tid * 4;
    float4 g4 = *(const float4*)(gam + d0);
    float4 b4 = *(const float4*)(bet + d0);
    float4 q4 = *(const float4*)(qp + (size_t)b * Dsz + d0);
    const float cbb = cbv[b];
    const float* base = video + (size_t)b * Fsz * Dsz + (size_t)chunk * 64 * Dsz;
    const int FH = 64;

    float m = -1e30f, l = 0.f;
    float4 acc = make_float4(0.f, 0.f, 0.f, 0.f);
    float4 x0 = *(const float4*)(base + d0);
    float4 x1 = *(const float4*)(base + Dsz + d0);

    for (int f = 0; f < FH; f += 2) {
        float4 n0 = x0, n1 = x1;
        if (f + 2 < FH) {
            n0 = *(const float4*)(base + (size_t)(f + 2) * Dsz + d0);
            n1 = *(const float4*)(base + (size_t)(f + 3) * Dsz + d0);
        }
        const int p = (f >> 1) & 1;
        float s0 = x0.x + x0.y + x0.z + x0.w;
        float q0 = x0.x * x0.x + x0.y * x0.y + x0.z * x0.z + x0.w * x0.w;
        float s1 = x1.x + x1.y + x1.z + x1.w;
        float q1 = x1.x * x1.x + x1.y * x1.y + x1.z * x1.z + x1.w * x1.w;
#pragma unroll
        for (int o = 16; o; o >>= 1) {
            s0 += __shfl_xor_sync(0xffffffffu, s0, o);
            q0 += __shfl_xor_sync(0xffffffffu, q0, o);
            s1 += __shfl_xor_sync(0xffffffffu, s1, o);
            q1 += __shfl_xor_sync(0xffffffffu, q1, o);
        }
        if (lane == 0) {
            red[p][0][w] = s0; red[p][1][w] = q0;
            red[p][2][w] = s1; red[p][3][w] = q1;
        }
        __syncthreads();
        float S0 = 0.f, Q0 = 0.f, S1 = 0.f, Q1 = 0.f;
#pragma unroll
        for (int i = 0; i < 8; ++i) {
            S0 += red[p][0][i]; Q0 += red[p][1][i];
            S1 += red[p][2][i]; Q1 += red[p][3][i];
        }
        const float mu0 = S0 * (1.0f / Dsz);
        const float r0 = rsqrtf(Q0 * (1.0f / Dsz) - mu0 * mu0 + 1e-5f);
        const float mu1 = S1 * (1.0f / Dsz);
        const float r1 = rsqrtf(Q1 * (1.0f / Dsz) - mu1 * mu1 + 1e-5f);
        float4 ln0, ln1;
        ln0.x = (x0.x - mu0) * r0 * g4.x + b4.x;
        ln0.y = (x0.y - mu0) * r0 * g4.y + b4.y;
        ln0.z = (x0.z - mu0) * r0 * g4.z + b4.z;
        ln0.w = (x0.w - mu0) * r0 * g4.w + b4.w;
        ln1.x = (x1.x - mu1) * r1 * g4.x + b4.x;
        ln1.y = (x1.y - mu1) * r1 * g4.y + b4.y;
        ln1.z = (x1.z - mu1) * r1 * g4.z + b4.z;
        ln1.w = (x1.w - mu1) * r1 * g4.w + b4.w;
        float d0p = ln0.x * q4.x + ln0.y * q4.y + ln0.z * q4.z + ln0.w * q4.w;
        float d1p = ln1.x * q4.x + ln1.y * q4.y + ln1.z * q4.z + ln1.w * q4.w;
#pragma unroll
        for (int o = 16; o; o >>= 1) {
            d0p += __shfl_xor_sync(0xffffffffu, d0p, o);
            d1p += __shfl_xor_sync(0xffffffffu, d1p, o);
        }
        if (lane == 0) { red[p][4][w] = d0p; red[p][5][w] = d1p; }
        __syncthreads();
        float dt0 = 0.f, dt1 = 0.f;
#pragma unroll
        for (int i = 0; i < 8; ++i) { dt0 += red[p][4][i]; dt1 += red[p][5][i]; }
        const float lg0 = (dt0 + cbb) * 0.03125f;
        const float lg1 = (dt1 + cbb) * 0.03125f;
        const float mn = fmaxf(m, fmaxf(lg0, lg1));
        const float alpha = __expf(m - mn);
        const float p0 = __expf(lg0 - mn);
        const float p1 = __expf(lg1 - mn);
        l = l * alpha + p0 + p1;
        acc.x = acc.x * alpha + p0 * ln0.x + p1 * ln1.x;
        acc.y = acc.y * alpha + p0 * ln0.y + p1 * ln1.y;
        acc.z = acc.z * alpha + p0 * ln0.z + p1 * ln1.z;
        acc.w = acc.w * alpha + p0 * ln0.w + p1 * ln1.w;
        m = mn;
        x0 = n0; x1 = n1;
    }
    *(float4*)(s2 + (size_t)chunk * MN + (size_t)b * Dsz + d0) = acc;
    if (tid == 0) { ml[b * 4 + chunk * 2] = m; ml[b * 4 + chunk * 2 + 1] = l; }
}

// ---------------- merge the two attention chunks ----------------------------
__global__ __launch_bounds__(256) void attn_merge(const float* __restrict__ s2,
                                                  const float* __restrict__ ml,
                                                  float* __restrict__ s_out) {
    const int b = blockIdx.x, d0 = threadIdx.x * 4;
    const float m0 = ml[b * 4 + 0], l0 = ml[b * 4 + 1];
    const float m1 = ml[b * 4 + 2], l1 = ml[b * 4 + 3];
    const float M = fmaxf(m0, m1);
    const float w0 = __expf(m0 - M), w1 = __expf(m1 - M);
    const float inv = 1.0f / (l0 * w0 + l1 * w1);
    float4 a0 = *(const float4*)(s2 + (size_t)b * Dsz + d0);
    float4 a1 = *(const float4*)(s2 + MN + (size_t)b * Dsz + d0);
    *(float4*)(s_out + (size_t)b * Dsz + d0) = make_float4(
        (a0.x * w0 + a1.x * w1) * inv, (a0.y * w0 + a1.y * w1) * inv,
        (a0.z * w0 + a1.z * w1) * inv, (a0.w * w0 + a1.w * w1) * inv);
}

// ---------------- driver -----------------------------------------------------
extern "C" void kernel_launch(void* const* d_in, const int* in_sizes, int n_in,
                              void* d_out, int out_size) {
    (void)in_sizes; (void)n_in; (void)out_size;
    const float* text  = (const float*)d_in[0];
    const float* video = (const float*)d_in[1];
    const float* q_w   = (const float*)d_in[2];
    const float* k_w   = (const float*)d_in[3];
    const float* v_w   = (const float*)d_in[4];
    const float* out_w = (const float*)d_in[5];
    const float* lin_w = (const float*)d_in[6];
    const float* q_b   = (const float*)d_in[7];
    const float* k_b   = (const float*)d_in[8];
    const float* v_b   = (const float*)d_in[9];
    const float* out_b = (const float*)d_in[10];
    const float* lin_b = (const float*)d_in[11];
    const float* ln1_g = (const float*)d_in[12];
    const float* ln1_b = (const float*)d_in[13];
    const float* ln2_g = (const float*)d_in[14];
    const float* ln2_b = (const float*)d_in[15];
    const float* ln3_g = (const float*)d_in[16];
    const float* ln3_b = (const float*)d_in[17];
    float* out = (float*)d_out;

    float *tln, *q, *qp, *cb, *s, *attn, *y, *aln, *z, *part, *kwt, *s2, *ml;
    cudaGetSymbolAddress((void**)&tln,  g_tln);
    cudaGetSymbolAddress((void**)&q,    g_q);
    cudaGetSymbolAddress((void**)&qp,   g_qp);
    cudaGetSymbolAddress((void**)&cb,   g_cb);
    cudaGetSymbolAddress((void**)&s,    g_s);
    cudaGetSymbolAddress((void**)&attn, g_attn);
    cudaGetSymbolAddress((void**)&y,    g_y);
    cudaGetSymbolAddress((void**)&aln,  g_aln);
    cudaGetSymbolAddress((void**)&z,    g_z);
    cudaGetSymbolAddress((void**)&part, g_part);
    cudaGetSymbolAddress((void**)&kwt,  g_kwt);
    cudaGetSymbolAddress((void**)&s2,   g_s2);
    cudaGetSymbolAddress((void**)&ml,   g_ml);

    cudaFuncSetAttribute(gemm_m, cudaFuncAttributeMaxDynamicSharedMemorySize, GM_SMEM);

    const dim3 gg(4, 8, TSPLIT);
    const int cgrid = MN / 4 / 256;  // 512

    // kwt = k_w.T  (independent; run first)
    transp<<<dim3(32, 32), dim3(32, 8)>>>(k_w, kwt);
    // t_ln = LN1(text)
    ln_rows<<<Bsz, 256>>>(text, tln, ln1_g, ln1_b);
    // q = t_ln @ q_w.T + q_b
    gemm_m<<<gg, 256, GM_SMEM>>>(tln, q_w, part);
    combine_k<true, false><<<cgrid, 256>>>(part, q_b, nullptr, q);
    // qp = q @ k_w = q @ (kwt).T
    gemm_m<<<gg, 256, GM_SMEM>>>(q, kwt, part);
    combine_k<false, false><<<cgrid, 256>>>(part, nullptr, nullptr, qp);
    // cb[b] = q[b] . k_b
    cb_k<<<Bsz, 256>>>(q, k_b, cb);
    // attention over LN1(video), 2 chunks per batch, then merge
    attn_fused<<<dim3(Bsz, 2), 256>>>(video, qp, cb, ln1_g, ln1_b, s2, ml);
    attn_merge<<<Bsz, 256>>>(s2, ml, s);
    // attn = s @ v_w.T + v_b
    gemm_m<<<gg, 256, GM_SMEM>>>(s, v_w, part);
    combine_k<true, false><<<cgrid, 256>>>(part, v_b, nullptr, attn);
    // y = attn @ out_w.T + out_b
    gemm_m<<<gg, 256, GM_SMEM>>>(attn, out_w, part);
    combine_k<true, false><<<cgrid, 256>>>(part, out_b, nullptr, y);
    // a_ln = LN2(y)
    ln_rows<<<Bsz, 256>>>(y, aln, ln2_g, ln2_b);
    // z = a_ln + a_ln @ lin_w.T + lin_b
    gemm_m<<<gg, 256, GM_SMEM>>>(aln, lin_w, part);
    combine_k<true, true><<<cgrid, 256>>>(part, lin_b, aln, z);
    // out = LN3(z)
    ln_rows<<<Bsz, 256>>>(z, out, ln3_g, ln3_b);
}